// round 9
// baseline (speedup 1.0000x reference)
#include <cuda_runtime.h>
#include <math_constants.h>

// MeanMaxPooling: N=4, E=64, L=512, D=256
// in[0]: doc_state    (N, L, D) float32
// in[1]: nodes_mapping(N, E, L) float32 (0/1)
// in[2]: nodes_len    (N, E)    float32  (== sum(mask); loaded first, fully hidden)
// out  : (N, E, 2*D)  float32  [0:D]=max over masked states (incl. 0), [D:2D]=mean
//
// CTA per (n,e): 16 warps = 8 token-chunks x 2 d-halves.
// Warp (c,h): tokens [64c,64c+64), d in [128h,128h+128). One LDG.128/lane/token,
// one predicated batch of 8 (E[sel]=6.4). 8-way merge, hoisted len, 16KB smem.

#define N_ 4
#define E_ 64
#define L_ 512
#define D_ 256
#define NC 8                  // token chunks (64 tokens each)
#define FULL_MASK 0xffffffffu

__global__ __launch_bounds__(512, 2)
void meanmax_kernel(const float* __restrict__ doc_state,
                    const float* __restrict__ nodes_mapping,
                    const float* __restrict__ nodes_len,
                    float* __restrict__ out)
{
    const int ne   = blockIdx.x;        // (n, e)
    const int n    = ne >> 6;
    const int tid  = threadIdx.x;
    const int w    = tid >> 5;
    const int c    = w & 7;             // token chunk: [64c, 64c+64)
    const int h    = w >> 3;            // d half: [128h, 128h+128)
    const int lane = tid & 31;

    __shared__ float s_max[NC][D_];     // 8 KB
    __shared__ float s_sum[NC][D_];     // 8 KB

    // first issue -> latency hidden behind the two memory round trips below
    const float len = nodes_len[ne];

    // warp reads its 64 mask values (two coalesced 128B lines) -> 64-bit mask
    const float* mrow = nodes_mapping + (size_t)ne * L_ + c * 64;
    const unsigned b0 = __ballot_sync(FULL_MASK, mrow[lane]      != 0.0f);
    const unsigned b1 = __ballot_sync(FULL_MASK, mrow[32 + lane] != 0.0f);
    unsigned long long mb = (unsigned long long)b0 |
                            ((unsigned long long)b1 << 32);

    // lane owns one float4 slot of its d-half in every token row
    const float4* doc4 = (const float4*)(doc_state + (size_t)n * L_ * D_)
                         + h * 32 + lane;
    const int base = c * 64;

    float4 sum = make_float4(0.f, 0.f, 0.f, 0.f);
    float4 mx  = make_float4(-CUDART_INF_F, -CUDART_INF_F,
                             -CUDART_INF_F, -CUDART_INF_F);

    // gather: E[selected] = 6.4 -> usually ONE batch of 8 independent LDG.128
    while (mb) {
        int  l[8];
        bool ok[8];
        #pragma unroll
        for (int j = 0; j < 8; ++j) {
            ok[j] = (mb != 0ull);
            l[j]  = ok[j] ? (__ffsll(mb) - 1) : 0;
            mb &= mb - 1ull;
        }
        float4 v[8];
        #pragma unroll
        for (int j = 0; j < 8; ++j)
            if (ok[j]) v[j] = doc4[(size_t)(base + l[j]) * (D_ / 4)];
        #pragma unroll
        for (int j = 0; j < 8; ++j) {
            if (ok[j]) {
                sum.x += v[j].x; sum.y += v[j].y;
                sum.z += v[j].z; sum.w += v[j].w;
                mx.x = fmaxf(mx.x, v[j].x); mx.y = fmaxf(mx.y, v[j].y);
                mx.z = fmaxf(mx.z, v[j].z); mx.w = fmaxf(mx.w, v[j].w);
            }
        }
    }

    // d-halves of the same chunk write disjoint 128-float ranges: no conflict
    *(float4*)&s_sum[c][h * 128 + 4 * lane] = sum;
    *(float4*)&s_max[c][h * 128 + 4 * lane] = mx;
    __syncthreads();

    // fully parallel merge: each of 512 threads owns ONE output scalar.
    // warps 0-7 -> max[d], warps 8-15 -> mean[d]; 8 LDS + 7 ops per thread.
    {
        const bool is_max = (tid < 256);
        const int  d = tid & 255;

        float r;
        if (is_max) {
            r = s_max[0][d];
            #pragma unroll
            for (int q = 1; q < NC; ++q) r = fmaxf(r, s_max[q][d]);
            if (len < (float)L_) r = fmaxf(r, 0.0f);  // masked-out tokens add 0
            out[(size_t)ne * (2 * D_) + d] = r;
        } else {
            r = s_sum[0][d];
            #pragma unroll
            for (int q = 1; q < NC; ++q) r += s_sum[q][d];
            r *= 1.0f / ((len > 0.0f) ? len : 1.0f);
            out[(size_t)ne * (2 * D_) + D_ + d] = r;
        }
    }
}

extern "C" void kernel_launch(void* const* d_in, const int* in_sizes, int n_in,
                              void* d_out, int out_size)
{
    const float* doc_state     = (const float*)d_in[0];
    const float* nodes_mapping = (const float*)d_in[1];
    const float* nodes_len     = (const float*)d_in[2];
    float* out = (float*)d_out;

    meanmax_kernel<<<N_ * E_, 512>>>(doc_state, nodes_mapping, nodes_len, out);
}

// round 10
// speedup vs baseline: 1.0072x; 1.0072x over previous
#include <cuda_runtime.h>
#include <math_constants.h>

// MeanMaxPooling: N=4, E=64, L=512, D=256
// in[0]: doc_state    (N, L, D) float32
// in[1]: nodes_mapping(N, E, L) float32 (0/1)
// in[2]: nodes_len    (N, E)    float32  (== sum(mask); loaded first, fully hidden)
// out  : (N, E, 2*D)  float32  [0:D]=max over masked states (incl. 0), [D:2D]=mean
//
// Empirical-best config (R3 shape): CTA per (n,e), 16 warps, warp w owns tokens
// [32w,32w+32) x full D. Ballot compaction, one batch of 4 tokens (8 indep
// LDG.128), single barrier, float4 merge by 128 threads, hoisted len.

#define N_ 4
#define E_ 64
#define L_ 512
#define D_ 256
#define NW 16
#define FULL_MASK 0xffffffffu

__global__ __launch_bounds__(NW * 32, 2)
void meanmax_kernel(const float* __restrict__ doc_state,
                    const float* __restrict__ nodes_mapping,
                    const float* __restrict__ nodes_len,
                    float* __restrict__ out)
{
    const int ne   = blockIdx.x;       // (n, e)
    const int n    = ne >> 6;
    const int tid  = threadIdx.x;
    const int w    = tid >> 5;         // 32-token chunk
    const int lane = tid & 31;

    __shared__ float4 s_sum[NW][64];   // [warp][d/4]  16 KB
    __shared__ float4 s_max[NW][64];   //              16 KB

    // first issue -> ~250-600cyc latency fully hidden behind mask+gather RTs
    const float len = nodes_len[ne];

    // warp reads its 32 mask values (one coalesced 128B line) -> bitmask
    const float mval = nodes_mapping[(size_t)ne * L_ + w * 32 + lane];
    unsigned mb = __ballot_sync(FULL_MASK, mval != 0.0f);

    const float4* doc4 = (const float4*)(doc_state + (size_t)n * L_ * D_);
    const int base = w * 32;

    float4 s0 = make_float4(0.f, 0.f, 0.f, 0.f), s1 = s0;
    float4 m0 = make_float4(-CUDART_INF_F, -CUDART_INF_F, -CUDART_INF_F, -CUDART_INF_F);
    float4 m1 = m0;

    // gather: E[selected]=3.2 -> usually ONE batch of 4 tokens (8 indep LDG.128)
    while (mb) {
        int  l[4];
        bool ok[4];
        #pragma unroll
        for (int j = 0; j < 4; ++j) {
            ok[j] = (mb != 0u);
            l[j]  = ok[j] ? (__ffs(mb) - 1) : 0;
            mb &= mb - 1u;
        }
        float4 a[4], b[4];
        #pragma unroll
        for (int j = 0; j < 4; ++j) {
            if (ok[j]) {
                const float4* p = doc4 + (size_t)(base + l[j]) * (D_ / 4);
                a[j] = p[lane];        // d = 4*lane..4*lane+3
                b[j] = p[32 + lane];   // d = 128+4*lane..
            }
        }
        #pragma unroll
        for (int j = 0; j < 4; ++j) {
            if (ok[j]) {
                s0.x += a[j].x; s0.y += a[j].y; s0.z += a[j].z; s0.w += a[j].w;
                s1.x += b[j].x; s1.y += b[j].y; s1.z += b[j].z; s1.w += b[j].w;
                m0.x = fmaxf(m0.x, a[j].x); m0.y = fmaxf(m0.y, a[j].y);
                m0.z = fmaxf(m0.z, a[j].z); m0.w = fmaxf(m0.w, a[j].w);
                m1.x = fmaxf(m1.x, b[j].x); m1.y = fmaxf(m1.y, b[j].y);
                m1.z = fmaxf(m1.z, b[j].z); m1.w = fmaxf(m1.w, b[j].w);
            }
        }
    }

    s_sum[w][lane]      = s0;
    s_sum[w][32 + lane] = s1;
    s_max[w][lane]      = m0;
    s_max[w][32 + lane] = m1;
    __syncthreads();

    // float4 merge: 128 threads, each owns one float4 output slot.
    // threads 0-63 -> max half, 64-127 -> mean half (uniform per warp-half).
    if (tid < 128) {
        const bool is_max = (tid < 64);
        const int  j = is_max ? tid : (tid - 64);   // float4 slot, 0..63

        float4 r = is_max ? s_max[0][j] : s_sum[0][j];
        #pragma unroll
        for (int q = 1; q < NW; ++q) {
            const float4 p = is_max ? s_max[q][j] : s_sum[q][j];
            if (is_max) {
                r.x = fmaxf(r.x, p.x); r.y = fmaxf(r.y, p.y);
                r.z = fmaxf(r.z, p.z); r.w = fmaxf(r.w, p.w);
            } else {
                r.x += p.x; r.y += p.y; r.z += p.z; r.w += p.w;
            }
        }

        float4* orow4 = (float4*)(out + (size_t)ne * (2 * D_));
        if (is_max) {
            if (len < (float)L_) {      // masked-out tokens contribute 0 to max
                r.x = fmaxf(r.x, 0.f); r.y = fmaxf(r.y, 0.f);
                r.z = fmaxf(r.z, 0.f); r.w = fmaxf(r.w, 0.f);
            }
            orow4[j] = r;
        } else {
            const float inv = 1.0f / ((len > 0.f) ? len : 1.f);
            r.x *= inv; r.y *= inv; r.z *= inv; r.w *= inv;
            orow4[(D_ / 4) + j] = r;
        }
    }
}

extern "C" void kernel_launch(void* const* d_in, const int* in_sizes, int n_in,
                              void* d_out, int out_size)
{
    const float* doc_state     = (const float*)d_in[0];
    const float* nodes_mapping = (const float*)d_in[1];
    const float* nodes_len     = (const float*)d_in[2];
    float* out = (float*)d_out;

    meanmax_kernel<<<N_ * E_, NW * 32>>>(doc_state, nodes_mapping, nodes_len, out);
}

// round 11
// speedup vs baseline: 1.3084x; 1.2991x over previous
#include <cuda_runtime.h>
#include <math_constants.h>

// MeanMaxPooling: N=4, E=64, L=512, D=256
// in[0]: doc_state    (N, L, D) float32
// in[1]: nodes_mapping(N, E, L) float32 (0/1)
// in[2]: nodes_len    (N, E)    float32
// out  : (N, E, 2*D)  float32  [0:D]=max over masked states (incl. 0), [D:2D]=mean
//
// Session-best config (R3): CTA per (n,e), 16 warps, warp w owns tokens
// [32w,32w+32) x full D. Ballot compaction (no atomics/barriers pre-gather),
// one predicated batch of 4 tokens (8 indep LDG.128), single barrier,
// float4 merge by 128 threads.

#define N_ 4
#define E_ 64
#define L_ 512
#define D_ 256
#define NW 16           // warps per CTA; warp w owns tokens [32w, 32w+32), full D

__global__ __launch_bounds__(NW * 32, 2)
void meanmax_kernel(const float* __restrict__ doc_state,
                    const float* __restrict__ nodes_mapping,
                    const float* __restrict__ nodes_len,
                    float* __restrict__ out)
{
    const int ne   = blockIdx.x;      // (n, e) pair
    const int n    = ne >> 6;         // ne / E
    const int tid  = threadIdx.x;
    const int w    = tid >> 5;        // warp = 32-token chunk
    const int lane = tid & 31;

    __shared__ float4 s_sum[NW][64];  // [warp][d/4]  16 KB
    __shared__ float4 s_max[NW][64];  //              16 KB

    // each warp reads its own 32 mask values -> in-warp bitmask; no barrier needed
    const float mval = nodes_mapping[(size_t)ne * L_ + w * 32 + lane];
    unsigned mb = __ballot_sync(0xffffffffu, mval != 0.0f);

    const float4* doc4 = (const float4*)(doc_state + (size_t)n * L_ * D_);
    const int base = w * 32;

    float4 s0 = make_float4(0.f, 0.f, 0.f, 0.f), s1 = s0;
    float4 m0 = make_float4(-CUDART_INF_F, -CUDART_INF_F, -CUDART_INF_F, -CUDART_INF_F);
    float4 m1 = m0;

    // gather: batches of 4 tokens (8 independent predicated 16B loads)
    while (mb) {
        int  l[4];
        bool ok[4];
        #pragma unroll
        for (int j = 0; j < 4; ++j) {
            ok[j] = (mb != 0u);
            l[j]  = ok[j] ? (__ffs(mb) - 1) : 0;
            mb &= mb - 1u;
        }
        float4 a[4], b[4];
        #pragma unroll
        for (int j = 0; j < 4; ++j) {
            if (ok[j]) {
                const float4* p = doc4 + (size_t)(base + l[j]) * (D_ / 4);
                a[j] = p[lane];        // d = 4*lane .. 4*lane+3
                b[j] = p[32 + lane];   // d = 128+4*lane ..
            }
        }
        #pragma unroll
        for (int j = 0; j < 4; ++j) {
            if (ok[j]) {
                s0.x += a[j].x; s0.y += a[j].y; s0.z += a[j].z; s0.w += a[j].w;
                s1.x += b[j].x; s1.y += b[j].y; s1.z += b[j].z; s1.w += b[j].w;
                m0.x = fmaxf(m0.x, a[j].x); m0.y = fmaxf(m0.y, a[j].y);
                m0.z = fmaxf(m0.z, a[j].z); m0.w = fmaxf(m0.w, a[j].w);
                m1.x = fmaxf(m1.x, b[j].x); m1.y = fmaxf(m1.y, b[j].y);
                m1.z = fmaxf(m1.z, b[j].z); m1.w = fmaxf(m1.w, b[j].w);
            }
        }
    }

    s_sum[w][lane]      = s0;
    s_sum[w][32 + lane] = s1;
    s_max[w][lane]      = m0;
    s_max[w][32 + lane] = m1;
    __syncthreads();

    // merge 16 partials; threads 0-63 -> max half, 64-127 -> sum half
    if (tid < 128) {
        const bool is_max = (tid < 64);
        const int  j = is_max ? tid : (tid - 64);   // float4 slot, 0..63

        float4 r = is_max ? s_max[0][j] : s_sum[0][j];
        #pragma unroll
        for (int q = 1; q < NW; ++q) {
            const float4 p = is_max ? s_max[q][j] : s_sum[q][j];
            if (is_max) {
                r.x = fmaxf(r.x, p.x); r.y = fmaxf(r.y, p.y);
                r.z = fmaxf(r.z, p.z); r.w = fmaxf(r.w, p.w);
            } else {
                r.x += p.x; r.y += p.y; r.z += p.z; r.w += p.w;
            }
        }

        const float len = nodes_len[ne];
        float4* orow = (float4*)(out + (size_t)ne * (2 * D_));
        if (is_max) {
            if (len < (float)L_) {      // any masked-out token => 0 participates in max
                r.x = fmaxf(r.x, 0.f); r.y = fmaxf(r.y, 0.f);
                r.z = fmaxf(r.z, 0.f); r.w = fmaxf(r.w, 0.f);
            }
            orow[j] = r;
        } else {
            const float inv = 1.0f / ((len > 0.f) ? len : 1.f);
            r.x *= inv; r.y *= inv; r.z *= inv; r.w *= inv;
            orow[(D_ / 4) + j] = r;
        }
    }
}

extern "C" void kernel_launch(void* const* d_in, const int* in_sizes, int n_in,
                              void* d_out, int out_size)
{
    const float* doc_state     = (const float*)d_in[0];
    const float* nodes_mapping = (const float*)d_in[1];
    const float* nodes_len     = (const float*)d_in[2];
    float* out = (float*)d_out;

    meanmax_kernel<<<N_ * E_, NW * 32>>>(doc_state, nodes_mapping, nodes_len, out);
}